// round 17
// baseline (speedup 1.0000x reference)
#include <cuda_runtime.h>
#include <cuda_fp16.h>
#include <math.h>
#include <stdint.h>

#define M_TOTAL 32768
#define E_DIM   512
#define F_DIM   2048

#define BM 128
#define BN 128
#define BK 64
#define THREADS 256
#define K_ITERS 32

// smem offsets (relative to 1024-aligned base)
#define SA0  0            // A (H fp16) [128 rows][128B] dbl: 2 x 16384
#define SAB  16384
#define SB0  32768        // B (W2 fp16) [128 rows][128B] dbl: 2 x 16384
#define SBB  16384
#define SMEM_BYTES (65536 + 1024)

// fp16 copy of W2 (E x F), row-major [n][k], uint4 = 8 halves
__device__ uint4 g_W2h[E_DIM * F_DIM / 8];

__global__ void cvt_w2_kernel(const float* __restrict__ W2) {
    int i = blockIdx.x * 256 + threadIdx.x;
    float4 v = ((const float4*)W2)[i];
    __half2* o = (__half2*)g_W2h;
    o[2 * i]     = __floats2half2_rn(v.x, v.y);
    o[2 * i + 1] = __floats2half2_rn(v.z, v.w);
}

static __device__ __forceinline__ uint32_t cvta_smem(const void* p) {
    uint32_t a;
    asm("{ .reg .u64 t; cvta.to.shared.u64 t, %1; cvt.u32.u64 %0, t; }" : "=r"(a) : "l"(p));
    return a;
}
static __device__ __forceinline__ void sts32(uint32_t addr, uint32_t v) {
    asm volatile("st.shared.b32 [%0], %1;" :: "r"(addr), "r"(v) : "memory");
}
static __device__ __forceinline__ void cpasync16(uint32_t dst, const void* src) {
    asm volatile("cp.async.ca.shared.global [%0], [%1], 16;"
                 :: "r"(dst), "l"(src) : "memory");
}
static __device__ __forceinline__ void ldsm4(uint32_t* r, uint32_t a) {
    asm volatile("ldmatrix.sync.aligned.m8n8.x4.shared.b16 {%0,%1,%2,%3}, [%4];"
                 : "=r"(r[0]), "=r"(r[1]), "=r"(r[2]), "=r"(r[3]) : "r"(a));
}
static __device__ __forceinline__ void mma_f16(float* c, const uint32_t* a,
                                               uint32_t b0, uint32_t b1) {
    asm volatile(
        "mma.sync.aligned.m16n8k16.row.col.f32.f16.f16.f32 "
        "{%0,%1,%2,%3},{%4,%5,%6,%7},{%8,%9},{%0,%1,%2,%3};"
        : "+f"(c[0]), "+f"(c[1]), "+f"(c[2]), "+f"(c[3])
        : "r"(a[0]), "r"(a[1]), "r"(a[2]), "r"(a[3]), "r"(b0), "r"(b1));
}
// d = A(k16, upper 8 zero) * B(n8k16, upper k zero); c = 0
static __device__ __forceinline__ void mma_f16_z(float* d, uint32_t a0, uint32_t a1,
                                                 uint32_t b0) {
    asm volatile(
        "mma.sync.aligned.m16n8k16.row.col.f32.f16.f16.f32 "
        "{%0,%1,%2,%3},{%4,%5,%6,%6},{%7,%6},{%8,%8,%8,%8};"
        : "=f"(d[0]), "=f"(d[1]), "=f"(d[2]), "=f"(d[3])
        : "r"(a0), "r"(a1), "r"(0u), "r"(b0), "f"(0.0f));
}

__global__ void __launch_bounds__(THREADS, 2)
ffq_kernel(const float* __restrict__ x,
           const float* __restrict__ theta,
           const float* __restrict__ W1,
           float* __restrict__ out)
{
    extern __shared__ char dsm[];
    const uint32_t raw = cvta_smem(dsm);
    const uint32_t sbase = (raw + 1023) & ~1023u;

    const int tid  = threadIdx.x;
    const int warp = tid >> 5, lane = tid & 31;
    const int g = lane >> 2, tq = lane & 3;
    const int wm = warp >> 2, wn = warp & 3;     // consumer: 2 x 4 grid, warp tile 64x32
    const int mt = blockIdx.x >> 2, nt = blockIdx.x & 3;
    const int m0 = mt * BM, n0 = nt * BN;

    // ---- q A-fragment (computed once): rows pr, pr+8; k = 2tq, 2tq+1 ----
    const int pr = warp * 16 + g;                // 0..127 across 8 warps; pr&7 == g
    uint32_t qf0, qf1;
    {
        const float t0 = __ldg(theta + 2 * tq);
        const float t1 = __ldg(theta + 2 * tq + 1);
        float2 v0 = *(const float2*)(x + (size_t)(m0 + pr) * E_DIM + 2 * tq);
        float2 v1 = *(const float2*)(x + (size_t)(m0 + pr + 8) * E_DIM + 2 * tq);
        __half2 h0 = __floats2half2_rn(cosf(2.0f * v0.x + t0), cosf(2.0f * v0.y + t1));
        __half2 h1 = __floats2half2_rn(cosf(2.0f * v1.x + t0), cosf(2.0f * v1.y + t1));
        qf0 = *(uint32_t*)&h0;
        qf1 = *(uint32_t*)&h1;
    }

    // ---- A producer STS bases: [128 rows][128B], swizzle chunk^(row&7); row&7 == g ----
    const uint32_t swp = (uint32_t)g;
    const uint32_t pBase0 = sbase + SA0 + pr * 128 + tq * 4;
    const uint32_t pBase1 = sbase + SA0 + (pr + 8) * 128 + tq * 4;

    // ---- B producer (R8-verified): row = tid>>1, 4 x 16B chunks at cb..cb+3 ----
    const int brow = tid >> 1;
    const int cb   = (tid & 1) * 4;
    const uint32_t bDst = sbase + SB0 + brow * 128;
    const uint4* gB = g_W2h + (size_t)(n0 + brow) * 256 + cb;
    uint32_t bcoff[4];
    #pragma unroll
    for (int j = 0; j < 4; ++j)
        bcoff[j] = ((uint32_t)((cb + j) ^ (brow & 7))) << 4;

    // ---- consumer constants (R8/R9-verified BK=64 mapping) ----
    const int t8 = lane >> 3, r8 = lane & 7;
    const int aCrow = wm * 64 + (t8 & 1) * 8 + r8;
    const uint32_t aCx = (uint32_t)(aCrow & 7);
    const uint32_t aCbase = sbase + SA0 + aCrow * 128;
    const int aCk = t8 >> 1;
    const int bCrow = wn * 32 + (t8 >> 1) * 8 + r8;
    const uint32_t bCx = (uint32_t)(bCrow & 7);
    const uint32_t bCbase = sbase + SB0 + bCrow * 128;
    const int bCk = t8 & 1;

    float acc[4][4][4];
    #pragma unroll
    for (int i = 0; i < 4; ++i)
        #pragma unroll
        for (int j = 0; j < 4; ++j)
            #pragma unroll
            for (int e = 0; e < 4; ++e) acc[i][j][e] = 0.0f;

    // ---- prologue: B(0) via cp.async; A(0) via producer MMA; wait; sync ----
    {
        #pragma unroll
        for (int j = 0; j < 4; ++j)
            cpasync16(bDst + bcoff[j], gB + j);
        asm volatile("cp.async.commit_group;" ::: "memory");

        #pragma unroll
        for (int t = 0; t < 8; ++t) {
            float2 w = *(const float2*)(W1 + (size_t)(8 * t + g) * 8 + 2 * tq);
            __half2 bh = __floats2half2_rn(w.x, w.y);
            float d[4];
            mma_f16_z(d, qf0, qf1, *(uint32_t*)&bh);
            __half2 h0 = __floats2half2_rn(fmaxf(d[0], 0.0f), fmaxf(d[1], 0.0f));
            __half2 h1 = __floats2half2_rn(fmaxf(d[2], 0.0f), fmaxf(d[3], 0.0f));
            sts32(pBase0 + ((((uint32_t)t) ^ swp) << 4), *(uint32_t*)&h0);
            sts32(pBase1 + ((((uint32_t)t) ^ swp) << 4), *(uint32_t*)&h1);
        }
        asm volatile("cp.async.wait_group 0;" ::: "memory");
    }
    __syncthreads();

    for (int it = 0; it < K_ITERS; ++it) {
        const int b = it & 1, nb = b ^ 1;
        const bool dp = (it + 1 < K_ITERS);
        const int kkn = (it + 1) * BK;

        // ---- top: kick off B(it+1) and produce A(it+1) (no smem reads) ----
        if (dp) {
            const uint32_t o = (uint32_t)nb * SBB;
            const uint4* src = gB + (size_t)(it + 1) * 8;
            #pragma unroll
            for (int j = 0; j < 4; ++j)
                cpasync16(bDst + o + bcoff[j], src + j);
            asm volatile("cp.async.commit_group;" ::: "memory");

            const uint32_t oa = (uint32_t)nb * SAB;
            #pragma unroll
            for (int t = 0; t < 8; ++t) {
                float2 w = *(const float2*)(W1 + (size_t)(kkn + 8 * t + g) * 8 + 2 * tq);
                __half2 bh = __floats2half2_rn(w.x, w.y);
                float d[4];
                mma_f16_z(d, qf0, qf1, *(uint32_t*)&bh);
                __half2 h0 = __floats2half2_rn(fmaxf(d[0], 0.0f), fmaxf(d[1], 0.0f));
                __half2 h1 = __floats2half2_rn(fmaxf(d[2], 0.0f), fmaxf(d[3], 0.0f));
                sts32(pBase0 + oa + ((((uint32_t)t) ^ swp) << 4), *(uint32_t*)&h0);
                sts32(pBase1 + oa + ((((uint32_t)t) ^ swp) << 4), *(uint32_t*)&h1);
            }
        }

        // ---- consume buffer b: 4 k16 blocks ----
        const uint32_t aoff = (uint32_t)b * SAB;
        const uint32_t boff = (uint32_t)b * SBB;
        #pragma unroll
        for (int ks = 0; ks < 4; ++ks) {
            uint32_t a[4][4];
            #pragma unroll
            for (int im = 0; im < 4; ++im)
                ldsm4(a[im], aCbase + aoff + im * 2048 +
                             ((((uint32_t)(ks * 2 + aCk)) ^ aCx) << 4));
            uint32_t bb[2][4];
            #pragma unroll
            for (int jp = 0; jp < 2; ++jp)
                ldsm4(bb[jp], bCbase + boff + jp * 2048 +
                              ((((uint32_t)(ks * 2 + bCk)) ^ bCx) << 4));
            #pragma unroll
            for (int im = 0; im < 4; ++im)
                #pragma unroll
                for (int jn = 0; jn < 4; ++jn)
                    mma_f16(acc[im][jn], a[im],
                            bb[jn >> 1][(jn & 1) * 2], bb[jn >> 1][(jn & 1) * 2 + 1]);
        }

        if (dp) asm volatile("cp.async.wait_group 0;" ::: "memory");
        __syncthreads();
    }

    // ---- epilogue (R6/R11-verified) ----
    #pragma unroll
    for (int im = 0; im < 4; ++im) {
        const int row0 = m0 + wm * 64 + im * 16 + g;
        #pragma unroll
        for (int jn = 0; jn < 4; ++jn) {
            const int col = n0 + wn * 32 + jn * 8 + tq * 2;
            *(float2*)(out + (size_t)row0 * E_DIM + col) =
                make_float2(acc[im][jn][0], acc[im][jn][1]);
            *(float2*)(out + (size_t)(row0 + 8) * E_DIM + col) =
                make_float2(acc[im][jn][2], acc[im][jn][3]);
        }
    }
}

extern "C" void kernel_launch(void* const* d_in, const int* in_sizes, int n_in,
                              void* d_out, int out_size) {
    const float* x     = (const float*)d_in[0];
    const float* theta = (const float*)d_in[1];
    const float* W1    = (const float*)d_in[2];
    const float* W2    = (const float*)d_in[3];
    float* out = (float*)d_out;

    cvt_w2_kernel<<<(E_DIM * F_DIM / 4) / 256, 256>>>(W2);

    cudaFuncSetAttribute(ffq_kernel, cudaFuncAttributeMaxDynamicSharedMemorySize, SMEM_BYTES);
    dim3 grid((M_TOTAL / BM) * (E_DIM / BN));   // 256 * 4 = 1024 CTAs
    ffq_kernel<<<grid, THREADS, SMEM_BYTES>>>(x, theta, W1, out);
}